// round 7
// baseline (speedup 1.0000x reference)
#include <cuda_runtime.h>
#include <cuda_bf16.h>

// Problem constants (fixed shapes per reference):
//   inputs  [256, 2048] fp32
//   targets [256] int64 (or int32, detected at runtime)
//   output  [256, 256, 256] fp32
#define N      256
#define D      2048
#define D4     (D / 4)        // 512 float4 per row
#define MARGIN 0.3f
#define EPSV   1e-12f
#define TILES  16             // N / 16
#define NPAIRS 136            // TILES*(TILES+1)/2 upper-triangular tile pairs

// Scratch (allocation-free: __device__ globals)
__device__ float g_sq[N];
__device__ float g_dist[N * N];
__device__ int   g_tgt[N];

// ---------------------------------------------------------------------------
// Kernel 0: normalize targets to int32 regardless of int64/int32 storage.
// Values are in [0,32). If the buffer is really int32, reading it as int64
// packs two labels per word -> values >= 2^32 with overwhelming probability.
// ---------------------------------------------------------------------------
__global__ void detect_targets_kernel(const void* __restrict__ traw) {
    int tid = threadIdx.x;  // 256 threads, 1 block
    long long v64 = ((const long long*)traw)[tid];
    int ok = (v64 >= 0 && v64 < 64) ? 1 : 0;
    int cnt = __syncthreads_count(ok);
    int v;
    if (cnt == N) {
        v = (int)v64;                       // genuine int64 layout
    } else {
        v = ((const int*)traw)[tid];        // int32 layout
    }
    g_tgt[tid] = v;
}

// ---------------------------------------------------------------------------
// Kernel 1: per-row squared norms. One block per row, 256 threads.
// ---------------------------------------------------------------------------
__global__ __launch_bounds__(256) void row_sq_kernel(const float* __restrict__ X) {
    int r = blockIdx.x;
    const float4* X4 = (const float4*)(X + (size_t)r * D);
    int tid = threadIdx.x;
    float4 v1 = X4[tid];
    float4 v2 = X4[tid + 256];
    float s = v1.x * v1.x + v1.y * v1.y + v1.z * v1.z + v1.w * v1.w +
              v2.x * v2.x + v2.y * v2.y + v2.z * v2.z + v2.w * v2.w;
#pragma unroll
    for (int o = 16; o > 0; o >>= 1) s += __shfl_down_sync(0xFFFFFFFFu, s, o);
    __shared__ float ws[8];
    if ((tid & 31) == 0) ws[tid >> 5] = s;
    __syncthreads();
    if (tid < 8) {
        s = ws[tid];
#pragma unroll
        for (int o = 4; o > 0; o >>= 1) s += __shfl_down_sync(0xFFu, s, o);
        if (tid == 0) g_sq[r] = s;
    }
}

// ---------------------------------------------------------------------------
// Kernel 2: pairwise Euclidean distance matrix via symmetric fp32 GEMM.
// Upper-triangular tile grid (136 blocks, one wave on 148 SMs), 16x16 output
// tiles, 256 threads, 1 output per thread, float4 k-vectorized smem reads.
// dist[i,j] = sqrt(max(sq_i + sq_j - 2*dot(i,j), 1e-12)); mirrored write.
// ---------------------------------------------------------------------------
__global__ __launch_bounds__(256) void tri_gemm_dist_kernel(const float* __restrict__ X) {
    // Decode linear upper-triangular tile index -> (bi, bj), bi <= bj
    int t = blockIdx.x;
    int bi = 0;
    while (t >= TILES - bi) { t -= TILES - bi; bi++; }
    int bj = bi + t;

    __shared__ float4 As[16 * 16];      // [row][k4]
    __shared__ float4 Bs[16 * 17];      // [row][k4], +1 float4 pad vs bank conflicts

    int tid = threadIdx.x;
    int ty = tid >> 4;       // 0..15 (output row within tile)
    int tx = tid & 15;       // 0..15 (output col within tile)

    const float4* X4 = (const float4*)X;
    int rowA = (bi * 16 + ty) * D4;     // load row = ty, load col = tx
    int rowB = (bj * 16 + ty) * D4;

    float a0 = 0.f, a1 = 0.f, a2 = 0.f, a3 = 0.f;  // 4 accum chains for ILP

    for (int k4 = 0; k4 < D4; k4 += 16) {
        As[ty * 16 + tx] = X4[rowA + k4 + tx];
        Bs[ty * 17 + tx] = X4[rowB + k4 + tx];
        __syncthreads();
#pragma unroll
        for (int kk = 0; kk < 16; kk++) {
            float4 a = As[ty * 16 + kk];
            float4 b = Bs[tx * 17 + kk];
            a0 = fmaf(a.x, b.x, a0);
            a1 = fmaf(a.y, b.y, a1);
            a2 = fmaf(a.z, b.z, a2);
            a3 = fmaf(a.w, b.w, a3);
        }
        __syncthreads();
    }
    float acc = (a0 + a1) + (a2 + a3);

    int i = bi * 16 + ty;
    int j = bj * 16 + tx;
    float d2 = g_sq[i] + g_sq[j] - 2.0f * acc;
    float d = sqrtf(fmaxf(d2, EPSV));
    g_dist[i * N + j] = d;
    g_dist[j * N + i] = d;   // symmetric mirror (idempotent on diagonal tiles)
}

// ---------------------------------------------------------------------------
// Kernel 3: expand to [a,p,n] with triplet margin + validity masking.
// out[a,p,n] = same(a,p)*diff(a,n)*max(d[a,p]-d[a,n]+MARGIN, 1e-12)
// grid (16 p-tiles, 256 a); block 256 threads handles 16 p-rows (16 KB).
// Stage dist row + mask in smem; streaming float4 stores (never re-read).
// ---------------------------------------------------------------------------
__global__ __launch_bounds__(256) void expand_writer_kernel(float* __restrict__ out) {
    int a  = blockIdx.y;
    int p0 = blockIdx.x * 16;
    int tid = threadIdx.x;

    __shared__ float ds[N];   // dist[a, n]
    __shared__ float ms[N];   // 1.0 if targets[n] != targets[a] else 0.0

    int ta = g_tgt[a];
    ds[tid] = g_dist[a * N + tid];
    ms[tid] = (g_tgt[tid] == ta) ? 0.0f : 1.0f;
    __syncthreads();

    int pl = tid >> 6;        // 0..3: which p within the pass
    int n4 = tid & 63;        // float4 index along n
    const float4* ds4 = (const float4*)ds;
    const float4* ms4 = (const float4*)ms;
    float4* out4 = (float4*)out;

#pragma unroll
    for (int pass = 0; pass < 4; pass++) {
        int p = p0 + pass * 4 + pl;
        float d_ap = ds[p];
        float s_ap = 1.0f - ms[p];         // same(a,p) flag as 0/1 float
        float c = d_ap + MARGIN;
        float4 dv = ds4[n4];
        float4 mv = ms4[n4];
        float4 o;
        o.x = s_ap * mv.x * fmaxf(c - dv.x, EPSV);
        o.y = s_ap * mv.y * fmaxf(c - dv.y, EPSV);
        o.z = s_ap * mv.z * fmaxf(c - dv.z, EPSV);
        o.w = s_ap * mv.w * fmaxf(c - dv.w, EPSV);
        // streaming store: evict-first, output never re-read
        __stcs(&out4[(size_t)a * (N * N / 4) + (size_t)p * (N / 4) + n4], o);
    }
}

// ---------------------------------------------------------------------------
extern "C" void kernel_launch(void* const* d_in, const int* in_sizes, int n_in,
                              void* d_out, int out_size) {
    // Identify inputs by element count (inputs: 256*2048, targets: 256)
    const float* X;
    const void*  T;
    if (in_sizes[0] == N) {
        T = d_in[0];
        X = (const float*)d_in[1];
    } else {
        X = (const float*)d_in[0];
        T = d_in[1];
    }
    float* out = (float*)d_out;

    detect_targets_kernel<<<1, 256>>>(T);
    row_sq_kernel<<<N, 256>>>(X);
    tri_gemm_dist_kernel<<<NPAIRS, 256>>>(X);
    dim3 wgrid(TILES, N);
    expand_writer_kernel<<<wgrid, 256>>>(out);
}

// round 9
// speedup vs baseline: 1.3498x; 1.3498x over previous
#include <cuda_runtime.h>
#include <cuda_bf16.h>

// Shapes fixed per reference:
//   inputs  [256, 2048] fp32, targets [256] int64/int32, output [256,256,256] fp32
#define N      256
#define D      2048
#define D4     (D / 4)
#define MARGIN 0.3f
#define EPSV   1e-12f

#define SPLITS  32            // split-K factor
#define KCHUNK  (D / SPLITS)  // 64 k per work item
#define SLABS   (KCHUNK / 16) // 4 smem slabs of 16 k
#define NPAIRS  10            // upper-tri pairs of 4x4 grid of 64x64 tiles

// Scratch (allocation-free: __device__ globals)
__device__ float g_sq[N];
__device__ float g_dist[N * N];
__device__ int   g_tgt[N];
__device__ float g_part[SPLITS * N * N];   // 8 MB split-K partial dots

// ---------------------------------------------------------------------------
// Kernel 0: normalize targets to int32 regardless of int64/int32 storage.
// ---------------------------------------------------------------------------
__global__ void detect_targets_kernel(const void* __restrict__ traw) {
    int tid = threadIdx.x;  // 256 threads, 1 block
    long long v64 = ((const long long*)traw)[tid];
    int ok = (v64 >= 0 && v64 < 64) ? 1 : 0;
    int cnt = __syncthreads_count(ok);
    int v;
    if (cnt == N) v = (int)v64;              // genuine int64 layout
    else          v = ((const int*)traw)[tid];  // int32 layout
    g_tgt[tid] = v;
}

// ---------------------------------------------------------------------------
// Kernel 1: per-row squared norms.
// ---------------------------------------------------------------------------
__global__ __launch_bounds__(256) void row_sq_kernel(const float* __restrict__ X) {
    int r = blockIdx.x;
    const float4* X4 = (const float4*)(X + (size_t)r * D);
    int tid = threadIdx.x;
    float4 v1 = X4[tid];
    float4 v2 = X4[tid + 256];
    float s = v1.x * v1.x + v1.y * v1.y + v1.z * v1.z + v1.w * v1.w +
              v2.x * v2.x + v2.y * v2.y + v2.z * v2.z + v2.w * v2.w;
#pragma unroll
    for (int o = 16; o > 0; o >>= 1) s += __shfl_down_sync(0xFFFFFFFFu, s, o);
    __shared__ float ws[8];
    if ((tid & 31) == 0) ws[tid >> 5] = s;
    __syncthreads();
    if (tid < 8) {
        s = ws[tid];
#pragma unroll
        for (int o = 4; o > 0; o >>= 1) s += __shfl_down_sync(0xFFu, s, o);
        if (tid == 0) g_sq[r] = s;
    }
}

// ---------------------------------------------------------------------------
// Kernel 2: split-K symmetric GEMM partials with FFMA2 (fma.rn.f32x2).
// Grid: NPAIRS * SPLITS = 320 blocks, 256 threads.
// Each block: 64x64 output tile (pair bi<=bj of the 4x4 tile grid) over a
// K-chunk of 64; 4x4 register tile per thread; packed f32x2 accumulators.
// ---------------------------------------------------------------------------
__device__ __forceinline__ void fma2(unsigned long long& acc,
                                     unsigned long long a,
                                     unsigned long long b) {
    asm("fma.rn.f32x2 %0, %1, %2, %0;" : "+l"(acc) : "l"(a), "l"(b));
}
__device__ __forceinline__ unsigned long long packdup(float a) {
    unsigned long long r;
    asm("mov.b64 %0, {%1, %1};" : "=l"(r) : "f"(a));
    return r;
}

__global__ __launch_bounds__(256) void gemm_part_kernel(const float* __restrict__ X) {
    int bx = blockIdx.x;
    int pair = bx % NPAIRS;
    int split = bx / NPAIRS;
    // decode upper-tri pair -> (bi, bj), bi <= bj, on 4x4 tile grid
    int t = pair, bi = 0;
    while (t >= 4 - bi) { t -= 4 - bi; bi++; }
    int bj = bi + t;

    __shared__ float As[16][68];   // [kk][row], pad 4 floats: 16B-aligned rows
    __shared__ float Bs[16][68];

    int tid = threadIdx.x;
    int ty = tid >> 4;            // 0..15 : output row group (4 rows)
    int tx = tid & 15;            // 0..15 : output col group (4 cols)
    int lrow = tid >> 2;          // 0..63 : load row   (coalesced LDG)
    int lkq  = tid & 3;           // 0..3  : load k-quad within slab

    const float4* X4 = (const float4*)X;
    int aBase = (bi * 64 + lrow) * D4 + split * (KCHUNK / 4) + lkq;
    int bBase = (bj * 64 + lrow) * D4 + split * (KCHUNK / 4) + lkq;

    unsigned long long c01[4], c23[4];   // c01[i]=(c[i][0],c[i][1]), c23[i]=(c[i][2],c[i][3])
#pragma unroll
    for (int i = 0; i < 4; i++) { c01[i] = 0ULL; c23[i] = 0ULL; }

#pragma unroll
    for (int s = 0; s < SLABS; s++) {
        float4 ga = X4[aBase + s * 4];
        float4 gb = X4[bBase + s * 4];
        int kk0 = lkq * 4;
        As[kk0 + 0][lrow] = ga.x; As[kk0 + 1][lrow] = ga.y;
        As[kk0 + 2][lrow] = ga.z; As[kk0 + 3][lrow] = ga.w;
        Bs[kk0 + 0][lrow] = gb.x; Bs[kk0 + 1][lrow] = gb.y;
        Bs[kk0 + 2][lrow] = gb.z; Bs[kk0 + 3][lrow] = gb.w;
        __syncthreads();
#pragma unroll
        for (int kk = 0; kk < 16; kk++) {
            float4 a = *(const float4*)&As[kk][ty * 4];
            ulonglong2 b = *(const ulonglong2*)&Bs[kk][tx * 4];
            unsigned long long aa;
            aa = packdup(a.x); fma2(c01[0], aa, b.x); fma2(c23[0], aa, b.y);
            aa = packdup(a.y); fma2(c01[1], aa, b.x); fma2(c23[1], aa, b.y);
            aa = packdup(a.z); fma2(c01[2], aa, b.x); fma2(c23[2], aa, b.y);
            aa = packdup(a.w); fma2(c01[3], aa, b.x); fma2(c23[3], aa, b.y);
        }
        __syncthreads();
    }

    // epilogue: write 4x4 partial dots to this split's partial buffer
    float* outp = g_part + split * (N * N);
    int gi0 = bi * 64 + ty * 4;
    int gj  = bj * 64 + tx * 4;
#pragma unroll
    for (int i = 0; i < 4; i++) {
        float lo0, lo1, hi0, hi1;
        asm("mov.b64 {%0, %1}, %2;" : "=f"(lo0), "=f"(lo1) : "l"(c01[i]));
        asm("mov.b64 {%0, %1}, %2;" : "=f"(hi0), "=f"(hi1) : "l"(c23[i]));
        float4 o = make_float4(lo0, lo1, hi0, hi1);
        *(float4*)&outp[(gi0 + i) * N + gj] = o;
    }
}

// ---------------------------------------------------------------------------
// Kernel 3: reduce split-K partials -> dist matrix (with symmetric mirror).
// Grid: NPAIRS * 16 = 160 blocks, 256 threads, 1 element each.
// ---------------------------------------------------------------------------
__global__ __launch_bounds__(256) void reduce_dist_kernel() {
    int bx = blockIdx.x;
    int pair = bx >> 4;
    int part = bx & 15;
    int t = pair, bi = 0;
    while (t >= 4 - bi) { t -= 4 - bi; bi++; }
    int bj = bi + t;

    int idx = part * 256 + threadIdx.x;   // 0..4095 within 64x64 tile
    int ii = idx >> 6, jj = idx & 63;
    int i = bi * 64 + ii, j = bj * 64 + jj;
    int off = i * N + j;

    float s0 = 0.f, s1 = 0.f, s2 = 0.f, s3 = 0.f;
#pragma unroll
    for (int s = 0; s < SPLITS; s += 4) {
        s0 += g_part[(s + 0) * (N * N) + off];
        s1 += g_part[(s + 1) * (N * N) + off];
        s2 += g_part[(s + 2) * (N * N) + off];
        s3 += g_part[(s + 3) * (N * N) + off];
    }
    float dot = (s0 + s1) + (s2 + s3);
    float d2 = g_sq[i] + g_sq[j] - 2.0f * dot;
    float d = sqrtf(fmaxf(d2, EPSV));
    g_dist[off] = d;
    g_dist[j * N + i] = d;   // idempotent on diagonal tiles
}

// ---------------------------------------------------------------------------
// Kernel 4: expand to [a,p,n]. Grid (4, 256) = 1024 blocks, 256 threads.
// Each block: anchor a, 64 consecutive p rows (16 KB of stores).
// dist row / mask held in registers per thread (n4 fixed), reused 16 passes.
// Default stores (no .cs): output stays resident in L2 (77MB WS < 126MB L2).
// ---------------------------------------------------------------------------
__global__ __launch_bounds__(256) void expand_writer_kernel(float* __restrict__ out) {
    int a  = blockIdx.y;
    int p0 = blockIdx.x * 64;
    int tid = threadIdx.x;

    __shared__ float ds[N];   // dist[a, n]
    __shared__ float ms[N];   // 1.0 if targets[n] != targets[a] else 0.0

    int ta = g_tgt[a];
    ds[tid] = g_dist[a * N + tid];
    ms[tid] = (g_tgt[tid] == ta) ? 0.0f : 1.0f;
    __syncthreads();

    int pl = tid >> 6;        // 0..3: p lane within a pass
    int n4 = tid & 63;        // float4 index along n
    float4 dv = ((const float4*)ds)[n4];   // hoisted: invariant across passes
    float4 mv = ((const float4*)ms)[n4];
    float4* out4 = (float4*)out + (size_t)a * (N * N / 4) + n4;

#pragma unroll
    for (int pass = 0; pass < 16; pass++) {
        int p = p0 + pass * 4 + pl;
        float s_ap = 1.0f - ms[p];         // same(a,p) as 0/1
        float c = ds[p] + MARGIN;
        float4 o;
        o.x = s_ap * mv.x * fmaxf(c - dv.x, EPSV);
        o.y = s_ap * mv.y * fmaxf(c - dv.y, EPSV);
        o.z = s_ap * mv.z * fmaxf(c - dv.z, EPSV);
        o.w = s_ap * mv.w * fmaxf(c - dv.w, EPSV);
        out4[(size_t)p * (N / 4)] = o;
    }
}

// ---------------------------------------------------------------------------
extern "C" void kernel_launch(void* const* d_in, const int* in_sizes, int n_in,
                              void* d_out, int out_size) {
    const float* X;
    const void*  T;
    if (in_sizes[0] == N) { T = d_in[0]; X = (const float*)d_in[1]; }
    else                  { X = (const float*)d_in[0]; T = d_in[1]; }
    float* out = (float*)d_out;

    detect_targets_kernel<<<1, 256>>>(T);
    row_sq_kernel<<<N, 256>>>(X);
    gemm_part_kernel<<<NPAIRS * SPLITS, 256>>>(X);
    reduce_dist_kernel<<<NPAIRS * 16, 256>>>();
    dim3 wgrid(4, N);
    expand_writer_kernel<<<wgrid, 256>>>(out);
}